// round 5
// baseline (speedup 1.0000x reference)
#include <cuda_runtime.h>
#include <cuda_bf16.h>
#include <cstdint>

#define TT   1024
#define BSZ  64
#define DD   256
#define HH   256
#define G4   1024            // 4*H
#define NBLK 128             // persistent recurrent blocks
#define TBH  (TT*BSZ*HH)
#define BH   (BSZ*HH)

typedef unsigned long long ull;

// Scratch (device globals: no runtime allocation allowed)
__device__ float    g_Z[(size_t)TT * BSZ * G4];   // [t][b][gate*256+u]  (256 MB)
__device__ float    g_hT[2][HH * BSZ];            // transposed hidden: [k][b], dbl-buffered
__device__ unsigned g_cnt;                        // global step counter (release/acquire)

#define FMA_F32X2(d, a, b, c) \
    asm("fma.rn.f32x2 %0, %1, %2, %3;" : "=l"(d) : "l"(a), "l"(b), "l"(c))
#define PACK2(d, lo, hi) \
    asm("mov.b64 %0, {%1, %2};" : "=l"(d) : "f"(lo), "f"(hi))
#define UNPACK2(lo, hi, s) \
    asm("mov.b64 {%0, %1}, %2;" : "=f"(lo), "=f"(hi) : "l"(s))

// ---------------------------------------------------------------------------
// Phase 1: Z[t][b][g*256+u] = bias_g[u] + sum_k x[t][b][k] * W_g[u*512 + k]
// GEMM M=65536 (t*64+b), N=1024, K=256. BM=128, BN=128, BK=16, 8x8 tiles.
// Also resets g_cnt (runs fully before lstm due to stream ordering).
// ---------------------------------------------------------------------------
__global__ __launch_bounds__(256, 2)
void proj_kernel(const float* __restrict__ x,
                 const float* __restrict__ Wf, const float* __restrict__ bf,
                 const float* __restrict__ Wi, const float* __restrict__ bi,
                 const float* __restrict__ Wg, const float* __restrict__ bg,
                 const float* __restrict__ Wo, const float* __restrict__ bo)
{
    __shared__ float As[16 * 132];
    __shared__ float Bs[16 * 132];

    const int tid = threadIdx.x;
    if (blockIdx.x == 0 && blockIdx.y == 0 && tid == 0) g_cnt = 0u;

    const int tx  = tid & 15;
    const int ty  = tid >> 4;
    const int bm    = blockIdx.y * 128;
    const int gate  = blockIdx.x >> 1;
    const int ucol0 = (blockIdx.x & 1) * 128;

    const float* W    = (gate == 0) ? Wf : (gate == 1) ? Wi : (gate == 2) ? Wg : Wo;
    const float* bias = (gate == 0) ? bf : (gate == 1) ? bi : (gate == 2) ? bg : bo;

    float acc[8][8];
#pragma unroll
    for (int i = 0; i < 8; i++)
#pragma unroll
        for (int j = 0; j < 8; j++) acc[i][j] = 0.f;

    for (int k0 = 0; k0 < 256; k0 += 16) {
#pragma unroll
        for (int it = 0; it < 2; it++) {
            int f4  = tid + it * 256;          // 512 float4 per tile
            int row = f4 >> 2;                 // 0..127
            int kc  = (f4 & 3) << 2;           // 0,4,8,12
            float4 av = *(const float4*)(x + (size_t)(bm + row) * 256 + k0 + kc);
            As[(kc + 0) * 132 + row] = av.x;
            As[(kc + 1) * 132 + row] = av.y;
            As[(kc + 2) * 132 + row] = av.z;
            As[(kc + 3) * 132 + row] = av.w;
            float4 bv = *(const float4*)(W + (size_t)(ucol0 + row) * 512 + k0 + kc);
            Bs[(kc + 0) * 132 + row] = bv.x;
            Bs[(kc + 1) * 132 + row] = bv.y;
            Bs[(kc + 2) * 132 + row] = bv.z;
            Bs[(kc + 3) * 132 + row] = bv.w;
        }
        __syncthreads();
#pragma unroll
        for (int kk = 0; kk < 16; kk++) {
            float4 a0 = *(const float4*)&As[kk * 132 + ty * 8];
            float4 a1 = *(const float4*)&As[kk * 132 + ty * 8 + 4];
            float4 b0 = *(const float4*)&Bs[kk * 132 + tx * 8];
            float4 b1 = *(const float4*)&Bs[kk * 132 + tx * 8 + 4];
            float a[8] = {a0.x, a0.y, a0.z, a0.w, a1.x, a1.y, a1.z, a1.w};
            float b[8] = {b0.x, b0.y, b0.z, b0.w, b1.x, b1.y, b1.z, b1.w};
#pragma unroll
            for (int i = 0; i < 8; i++)
#pragma unroll
                for (int j = 0; j < 8; j++) acc[i][j] += a[i] * b[j];
        }
        __syncthreads();
    }

    float4 q0 = *(const float4*)(bias + ucol0 + tx * 8);
    float4 q1 = *(const float4*)(bias + ucol0 + tx * 8 + 4);
    float bb[8] = {q0.x, q0.y, q0.z, q0.w, q1.x, q1.y, q1.z, q1.w};

#pragma unroll
    for (int i = 0; i < 8; i++) {
        size_t m  = (size_t)(bm + ty * 8 + i);
        float* zp = g_Z + m * 1024 + gate * 256 + ucol0 + tx * 8;
        float4 v0 = {acc[i][0] + bb[0], acc[i][1] + bb[1], acc[i][2] + bb[2], acc[i][3] + bb[3]};
        float4 v1 = {acc[i][4] + bb[4], acc[i][5] + bb[5], acc[i][6] + bb[6], acc[i][7] + bb[7]};
        *(float4*)zp       = v0;
        *(float4*)(zp + 4) = v1;
    }
}

// ---------------------------------------------------------------------------
// Phase 2: persistent recurrence. 128 blocks x 512 threads.
// Block owns hidden units {2*blk, 2*blk+1} -> 8 gate cols (4 gates x 2 units).
// warp w -> batches [4w, 4w+4); lane -> k-set {lane + 32j, j=0..7}.
// Weights in regs as f32x2 packed over the 2 units: wp[gate][j].
// Per j: one LDG.128 of h (4 batches from g_hT[k][b], L2), 4 dup-packs,
// 16 FFMA2 -> each h value feeds all 8 cols. h traffic = 64KB/block/step
// (minimum). Partial sums reduced across the 32 lanes by butterfly fold
// (lane l ends holding output index l = c*4+bq).
// ---------------------------------------------------------------------------
__device__ __forceinline__ float sig_(float v)  { return __fdividef(1.f, 1.f + __expf(-v)); }
__device__ __forceinline__ float tanh_(float v) { return __fdividef(2.f, 1.f + __expf(-2.f * v)) - 1.f; }

__global__ __launch_bounds__(512, 1)
void lstm_kernel(const float* __restrict__ Wf, const float* __restrict__ Wi,
                 const float* __restrict__ Wg, const float* __restrict__ Wo,
                 float* __restrict__ out)
{
    __shared__ float pre[8 * 65];      // [c][b], stride 65

    const int tid  = threadIdx.x;
    const int blk  = blockIdx.x;
    const int u0   = blk * 2;
    const int lane = tid & 31;
    const int warp = tid >> 5;

    // ---- load recurrent weights into registers, packed {u0, u0+1} ----
    const float* Ws[4] = {Wf, Wi, Wg, Wo};
    ull wp[4][8];
#pragma unroll
    for (int g = 0; g < 4; g++) {
        const float* W0 = Ws[g] + (size_t)u0 * 512 + 256;
        const float* W1 = Ws[g] + (size_t)(u0 + 1) * 512 + 256;
#pragma unroll
        for (int j = 0; j < 8; j++) {
            int k = lane + 32 * j;
            PACK2(wp[g][j], W0[k], W1[k]);
        }
    }

    float2 cst = {0.f, 0.f};

    for (int t = 0; t < TT; t++) {
        // Prefetch Z (independent of h) before waiting on the counter
        float2 zf, zi, zg, zo;
        if (tid < 64) {
            const float* zr = g_Z + ((size_t)t * 64 + tid) * 1024 + u0;
            zf = __ldcs((const float2*)(zr));
            zi = __ldcs((const float2*)(zr + 256));
            zg = __ldcs((const float2*)(zr + 512));
            zo = __ldcs((const float2*)(zr + 768));
        }

        if (t > 0) {
            // Acquire: wait for all 128 blocks to have finished step t-1
            if (tid == 0) {
                unsigned target = (unsigned)(NBLK * t);
                unsigned vv;
                do {
                    asm volatile("ld.acquire.gpu.global.u32 %0, [%1];"
                                 : "=r"(vv) : "l"(&g_cnt) : "memory");
                } while (vv < target);
            }
            __syncthreads();

            // ---- GEMM: acc2[g][b] over this lane's 8 k's ----
            const float4* hp = (const float4*)&g_hT[t & 1][0];
            ull acc2[4][4];
#pragma unroll
            for (int g = 0; g < 4; g++)
#pragma unroll
                for (int b = 0; b < 4; b++) acc2[g][b] = 0ull;

#pragma unroll
            for (int j = 0; j < 8; j++) {
                int k = lane + 32 * j;
                float4 h4 = __ldcg(&hp[k * 16 + warp]);   // h[k][4w..4w+3]
                ull hd0, hd1, hd2, hd3;
                PACK2(hd0, h4.x, h4.x);
                PACK2(hd1, h4.y, h4.y);
                PACK2(hd2, h4.z, h4.z);
                PACK2(hd3, h4.w, h4.w);
#pragma unroll
                for (int g = 0; g < 4; g++) {
                    FMA_F32X2(acc2[g][0], wp[g][j], hd0, acc2[g][0]);
                    FMA_F32X2(acc2[g][1], wp[g][j], hd1, acc2[g][1]);
                    FMA_F32X2(acc2[g][2], wp[g][j], hd2, acc2[g][2]);
                    FMA_F32X2(acc2[g][3], wp[g][j], hd3, acc2[g][3]);
                }
            }

            // ---- unpack to 32 scalars: a[m], m = c*4 + bq, c = g*2+v ----
            float a[32];
#pragma unroll
            for (int g = 0; g < 4; g++)
#pragma unroll
                for (int b = 0; b < 4; b++) {
                    float lo, hi;
                    UNPACK2(lo, hi, acc2[g][b]);
                    a[(2 * g + 0) * 4 + b] = lo;
                    a[(2 * g + 1) * 4 + b] = hi;
                }

            // ---- butterfly fold across 32 lanes: lane l -> output m = l ----
#pragma unroll
            for (int d = 16; d >= 1; d >>= 1) {
#pragma unroll
                for (int jj = 0; jj < d; jj++) {
                    bool hi_l = (lane & d) != 0;
                    float send = hi_l ? a[jj] : a[jj + d];
                    float recv = __shfl_xor_sync(0xffffffffu, send, d);
                    float keep = hi_l ? a[jj + d] : a[jj];
                    a[jj] = keep + recv;
                }
            }
            // lane holds pre for c = lane>>2, b = warp*4 + (lane&3)
            pre[(lane >> 2) * 65 + warp * 4 + (lane & 3)] = a[0];
        } else {
            if (tid < 64) {
#pragma unroll
                for (int cc = 0; cc < 8; cc++) pre[cc * 65 + tid] = 0.f;
            }
        }
        __syncthreads();

        if (tid < 64) {
            const int b_e = tid;
            float f0 = sig_ (pre[0 * 65 + b_e] + zf.x);
            float f1 = sig_ (pre[1 * 65 + b_e] + zf.y);
            float i0 = sig_ (pre[2 * 65 + b_e] + zi.x);
            float i1 = sig_ (pre[3 * 65 + b_e] + zi.y);
            float g0 = tanh_(pre[4 * 65 + b_e] + zg.x);
            float g1 = tanh_(pre[5 * 65 + b_e] + zg.y);
            float o0 = sig_ (pre[6 * 65 + b_e] + zo.x);
            float o1 = sig_ (pre[7 * 65 + b_e] + zo.y);
            cst.x = f0 * cst.x + i0 * g0;
            cst.y = f1 * cst.y + i1 * g1;
            float h0 = o0 * tanh_(cst.x);
            float h1 = o1 * tanh_(cst.y);
            float* hT = g_hT[(t + 1) & 1];
            hT[(u0 + 0) * 64 + b_e] = h0;       // coalesced 256B per row
            hT[(u0 + 1) * 64 + b_e] = h1;
            float2 h2 = {h0, h1};
            *(float2*)&out[((size_t)t * 64 + b_e) * 256 + u0] = h2;
            if (t == TT - 1) {
                *(float2*)&out[TBH + b_e * 256 + u0]      = h2;
                *(float2*)&out[TBH + BH + b_e * 256 + u0] = cst;
            }
        }

        __syncthreads();     // epilogue stores done before release
        if (tid == 0) {
            asm volatile("red.release.gpu.global.add.u32 [%0], %1;"
                         :: "l"(&g_cnt), "r"(1u) : "memory");
        }
    }
}

// ---------------------------------------------------------------------------
// Launch
// ---------------------------------------------------------------------------
extern "C" void kernel_launch(void* const* d_in, const int* in_sizes, int n_in,
                              void* d_out, int out_size)
{
    const float* x  = (const float*)d_in[0];
    const float* Wf = (const float*)d_in[1];
    const float* bf = (const float*)d_in[2];
    const float* Wi = (const float*)d_in[3];
    const float* bi = (const float*)d_in[4];
    const float* Wg = (const float*)d_in[5];
    const float* bg = (const float*)d_in[6];
    const float* Wo = (const float*)d_in[7];
    const float* bo = (const float*)d_in[8];
    float* out = (float*)d_out;

    proj_kernel<<<dim3(8, 512), 256>>>(x, Wf, bf, Wi, bi, Wg, bg, Wo, bo);
    lstm_kernel<<<NBLK, 512>>>(Wf, Wi, Wg, Wo, out);
}

// round 6
// speedup vs baseline: 1.0460x; 1.0460x over previous
#include <cuda_runtime.h>
#include <cuda_bf16.h>
#include <cstdint>

#define TT   1024
#define BSZ  64
#define DD   256
#define HH   256
#define G4   1024            // 4*H
#define NBLK 128             // persistent recurrent blocks
#define TBH  (TT*BSZ*HH)
#define BH   (BSZ*HH)

typedef unsigned long long ull;

// Scratch (device globals: no runtime allocation allowed)
__device__ float    g_Z[(size_t)TT * BSZ * G4];   // [t][b][gate*256+u]  (256 MB)
__device__ float    g_h[2][BSZ * HH];             // hidden [b][k], double-buffered
__device__ unsigned g_cnt;                        // global step counter (release/acquire)

#define FMA_F32X2(d, a, b, c) \
    asm("fma.rn.f32x2 %0, %1, %2, %3;" : "=l"(d) : "l"(a), "l"(b), "l"(c))
#define ADD_F32X2(d, a, b) \
    asm("add.rn.f32x2 %0, %1, %2;" : "=l"(d) : "l"(a), "l"(b))
#define PACK2(d, lo, hi) \
    asm("mov.b64 %0, {%1, %2};" : "=l"(d) : "f"(lo), "f"(hi))
#define UNPACK2(lo, hi, s) \
    asm("mov.b64 {%0, %1}, %2;" : "=f"(lo), "=f"(hi) : "l"(s))

// ---------------------------------------------------------------------------
// Phase 1: Z[t][b][g*256+u] = bias_g[u] + sum_k x[t][b][k] * W_g[u*512 + k]
// GEMM M=65536 (t*64+b), N=1024, K=256. BM=128, BN=128, BK=16, 8x8 tiles.
// Also resets g_cnt (runs fully before lstm due to stream ordering).
// ---------------------------------------------------------------------------
__global__ __launch_bounds__(256, 2)
void proj_kernel(const float* __restrict__ x,
                 const float* __restrict__ Wf, const float* __restrict__ bf,
                 const float* __restrict__ Wi, const float* __restrict__ bi,
                 const float* __restrict__ Wg, const float* __restrict__ bg,
                 const float* __restrict__ Wo, const float* __restrict__ bo)
{
    __shared__ float As[16 * 132];
    __shared__ float Bs[16 * 132];

    const int tid = threadIdx.x;
    if (blockIdx.x == 0 && blockIdx.y == 0 && tid == 0) g_cnt = 0u;

    const int tx  = tid & 15;
    const int ty  = tid >> 4;
    const int bm    = blockIdx.y * 128;
    const int gate  = blockIdx.x >> 1;
    const int ucol0 = (blockIdx.x & 1) * 128;

    const float* W    = (gate == 0) ? Wf : (gate == 1) ? Wi : (gate == 2) ? Wg : Wo;
    const float* bias = (gate == 0) ? bf : (gate == 1) ? bi : (gate == 2) ? bg : bo;

    float acc[8][8];
#pragma unroll
    for (int i = 0; i < 8; i++)
#pragma unroll
        for (int j = 0; j < 8; j++) acc[i][j] = 0.f;

    for (int k0 = 0; k0 < 256; k0 += 16) {
#pragma unroll
        for (int it = 0; it < 2; it++) {
            int f4  = tid + it * 256;          // 512 float4 per tile
            int row = f4 >> 2;                 // 0..127
            int kc  = (f4 & 3) << 2;           // 0,4,8,12
            float4 av = *(const float4*)(x + (size_t)(bm + row) * 256 + k0 + kc);
            As[(kc + 0) * 132 + row] = av.x;
            As[(kc + 1) * 132 + row] = av.y;
            As[(kc + 2) * 132 + row] = av.z;
            As[(kc + 3) * 132 + row] = av.w;
            float4 bv = *(const float4*)(W + (size_t)(ucol0 + row) * 512 + k0 + kc);
            Bs[(kc + 0) * 132 + row] = bv.x;
            Bs[(kc + 1) * 132 + row] = bv.y;
            Bs[(kc + 2) * 132 + row] = bv.z;
            Bs[(kc + 3) * 132 + row] = bv.w;
        }
        __syncthreads();
#pragma unroll
        for (int kk = 0; kk < 16; kk++) {
            float4 a0 = *(const float4*)&As[kk * 132 + ty * 8];
            float4 a1 = *(const float4*)&As[kk * 132 + ty * 8 + 4];
            float4 b0 = *(const float4*)&Bs[kk * 132 + tx * 8];
            float4 b1 = *(const float4*)&Bs[kk * 132 + tx * 8 + 4];
            float a[8] = {a0.x, a0.y, a0.z, a0.w, a1.x, a1.y, a1.z, a1.w};
            float b[8] = {b0.x, b0.y, b0.z, b0.w, b1.x, b1.y, b1.z, b1.w};
#pragma unroll
            for (int i = 0; i < 8; i++)
#pragma unroll
                for (int j = 0; j < 8; j++) acc[i][j] += a[i] * b[j];
        }
        __syncthreads();
    }

    float4 q0 = *(const float4*)(bias + ucol0 + tx * 8);
    float4 q1 = *(const float4*)(bias + ucol0 + tx * 8 + 4);
    float bb[8] = {q0.x, q0.y, q0.z, q0.w, q1.x, q1.y, q1.z, q1.w};

#pragma unroll
    for (int i = 0; i < 8; i++) {
        size_t m  = (size_t)(bm + ty * 8 + i);
        float* zp = g_Z + m * 1024 + gate * 256 + ucol0 + tx * 8;
        float4 v0 = {acc[i][0] + bb[0], acc[i][1] + bb[1], acc[i][2] + bb[2], acc[i][3] + bb[3]};
        float4 v1 = {acc[i][4] + bb[4], acc[i][5] + bb[5], acc[i][6] + bb[6], acc[i][7] + bb[7]};
        *(float4*)zp       = v0;
        *(float4*)(zp + 4) = v1;
    }
}

// ---------------------------------------------------------------------------
// Phase 2: persistent recurrence. 128 blocks x 512 threads.
// Block owns hidden units {2*blk, 2*blk+1} -> 8 gate cols (4 gates x 2 units).
// Stage h (64KB) linearly into SMEM (coalesced LDG.128), then:
//   warp w -> batches [4w, 4w+4); lane -> k in [8*lane, 8*lane+8).
//   Weights for all 8 cols in regs as f32x2 (packed over the 2 units).
//   Each h value read ONCE (2 contiguous LDS.128/batch), feeds 8 cols (FFMA2).
//   Distributing butterfly fold (d=16,8 route gates; d=4,2,1 reduce):
//   lane class (bit4,bit3) ends with gate g = 2*bit4 + bit3 fully reduced.
// ---------------------------------------------------------------------------
__device__ __forceinline__ float sig_(float v)  { return __fdividef(1.f, 1.f + __expf(-v)); }
__device__ __forceinline__ float tanh_(float v) { return __fdividef(2.f, 1.f + __expf(-2.f * v)) - 1.f; }

#define HS_FLOATS (BSZ * HH)             // 16384 floats = 64KB
#define SMEM_FLOATS (HS_FLOATS + 8 * 65)

__global__ __launch_bounds__(512, 1)
void lstm_kernel(const float* __restrict__ Wf, const float* __restrict__ Wi,
                 const float* __restrict__ Wg, const float* __restrict__ Wo,
                 float* __restrict__ out)
{
    extern __shared__ float smem[];
    float* hs  = smem;                   // [b][k] linear copy of g_h
    float* pre = smem + HS_FLOATS;       // [c][b], stride 65

    const int tid  = threadIdx.x;
    const int blk  = blockIdx.x;
    const int u0   = blk * 2;
    const int lane = tid & 31;
    const int warp = tid >> 5;

    // ---- recurrent weights in registers, f32x2 packed over {u0, u0+1} ----
    const float* Ws[4] = {Wf, Wi, Wg, Wo};
    ull wp[4][8];
#pragma unroll
    for (int g = 0; g < 4; g++) {
        const float* W0 = Ws[g] + (size_t)u0 * 512 + 256;
        const float* W1 = Ws[g] + (size_t)(u0 + 1) * 512 + 256;
#pragma unroll
        for (int j = 0; j < 8; j++) {
            int k = lane * 8 + j;
            PACK2(wp[g][j], W0[k], W1[k]);
        }
    }

    const bool hi4 = (lane & 16) != 0;
    const bool hi3 = (lane & 8) != 0;
    const int  gsel = 2 * (int)hi4 + (int)hi3;   // gate this lane-class reports

    float2 cst = {0.f, 0.f};

    for (int t = 0; t < TT; t++) {
        // Prefetch Z (independent of h) before waiting on the counter
        float2 zf, zi, zg, zo;
        if (tid < 64) {
            const float* zr = g_Z + ((size_t)t * 64 + tid) * 1024 + u0;
            zf = __ldcs((const float2*)(zr));
            zi = __ldcs((const float2*)(zr + 256));
            zg = __ldcs((const float2*)(zr + 512));
            zo = __ldcs((const float2*)(zr + 768));
        }

        if (t > 0) {
            // Acquire: wait for all 128 blocks to have finished step t-1
            if (tid == 0) {
                unsigned target = (unsigned)(NBLK * t);
                unsigned vv;
                do {
                    asm volatile("ld.acquire.gpu.global.u32 %0, [%1];"
                                 : "=r"(vv) : "l"(&g_cnt) : "memory");
                } while (vv < target);
            }
            __syncthreads();

            // ---- stage h -> SMEM, linear coalesced (8 LDG.128 / thread) ----
            const float4* hsrc = (const float4*)&g_h[t & 1][0];
            float4*       hdst = (float4*)hs;
#pragma unroll
            for (int i = 0; i < 8; i++) {
                int f4 = tid + i * 512;               // 4096 float4 total
                hdst[f4] = __ldcg(&hsrc[f4]);
            }
            __syncthreads();

            // ---- compute 4 batches for this warp ----
#pragma unroll
            for (int b4 = 0; b4 < 4; b4++) {
                int bb = warp * 4 + b4;
                const float4* hb = (const float4*)&hs[bb * 256 + lane * 8];
                float4 ha = hb[0];
                float4 hc = hb[1];

                ull acc0 = 0, acc1 = 0, acc2v = 0, acc3 = 0;
                ull hd;
                PACK2(hd, ha.x, ha.x);
                FMA_F32X2(acc0, wp[0][0], hd, acc0);
                FMA_F32X2(acc1, wp[1][0], hd, acc1);
                FMA_F32X2(acc2v, wp[2][0], hd, acc2v);
                FMA_F32X2(acc3, wp[3][0], hd, acc3);
                PACK2(hd, ha.y, ha.y);
                FMA_F32X2(acc0, wp[0][1], hd, acc0);
                FMA_F32X2(acc1, wp[1][1], hd, acc1);
                FMA_F32X2(acc2v, wp[2][1], hd, acc2v);
                FMA_F32X2(acc3, wp[3][1], hd, acc3);
                PACK2(hd, ha.z, ha.z);
                FMA_F32X2(acc0, wp[0][2], hd, acc0);
                FMA_F32X2(acc1, wp[1][2], hd, acc1);
                FMA_F32X2(acc2v, wp[2][2], hd, acc2v);
                FMA_F32X2(acc3, wp[3][2], hd, acc3);
                PACK2(hd, ha.w, ha.w);
                FMA_F32X2(acc0, wp[0][3], hd, acc0);
                FMA_F32X2(acc1, wp[1][3], hd, acc1);
                FMA_F32X2(acc2v, wp[2][3], hd, acc2v);
                FMA_F32X2(acc3, wp[3][3], hd, acc3);
                PACK2(hd, hc.x, hc.x);
                FMA_F32X2(acc0, wp[0][4], hd, acc0);
                FMA_F32X2(acc1, wp[1][4], hd, acc1);
                FMA_F32X2(acc2v, wp[2][4], hd, acc2v);
                FMA_F32X2(acc3, wp[3][4], hd, acc3);
                PACK2(hd, hc.y, hc.y);
                FMA_F32X2(acc0, wp[0][5], hd, acc0);
                FMA_F32X2(acc1, wp[1][5], hd, acc1);
                FMA_F32X2(acc2v, wp[2][5], hd, acc2v);
                FMA_F32X2(acc3, wp[3][5], hd, acc3);
                PACK2(hd, hc.z, hc.z);
                FMA_F32X2(acc0, wp[0][6], hd, acc0);
                FMA_F32X2(acc1, wp[1][6], hd, acc1);
                FMA_F32X2(acc2v, wp[2][6], hd, acc2v);
                FMA_F32X2(acc3, wp[3][6], hd, acc3);
                PACK2(hd, hc.w, hc.w);
                FMA_F32X2(acc0, wp[0][7], hd, acc0);
                FMA_F32X2(acc1, wp[1][7], hd, acc1);
                FMA_F32X2(acc2v, wp[2][7], hd, acc2v);
                FMA_F32X2(acc3, wp[3][7], hd, acc3);

                // ---- distributing fold ----
                // d=16: lo lanes accumulate gates {0,1}, hi lanes {2,3}
                ull s, r, kkp, v0, v1;
                s = hi4 ? acc0 : acc2v;
                r = __shfl_xor_sync(0xffffffffu, s, 16);
                kkp = hi4 ? acc2v : acc0;
                ADD_F32X2(v0, kkp, r);
                s = hi4 ? acc1 : acc3;
                r = __shfl_xor_sync(0xffffffffu, s, 16);
                kkp = hi4 ? acc3 : acc1;
                ADD_F32X2(v1, kkp, r);
                // d=8: lo keeps base+0, hi keeps base+1
                s = hi3 ? v0 : v1;
                r = __shfl_xor_sync(0xffffffffu, s, 8);
                kkp = hi3 ? v1 : v0;
                ADD_F32X2(v0, kkp, r);
                // d=4,2,1: pure reduction
                r = __shfl_xor_sync(0xffffffffu, v0, 4);  ADD_F32X2(v0, v0, r);
                r = __shfl_xor_sync(0xffffffffu, v0, 2);  ADD_F32X2(v0, v0, r);
                r = __shfl_xor_sync(0xffffffffu, v0, 1);  ADD_F32X2(v0, v0, r);

                if ((lane & 7) == 0) {
                    float lo, hi;
                    UNPACK2(lo, hi, v0);
                    pre[(2 * gsel + 0) * 65 + bb] = lo;
                    pre[(2 * gsel + 1) * 65 + bb] = hi;
                }
            }
        } else {
            if (tid < 64) {
#pragma unroll
                for (int cc = 0; cc < 8; cc++) pre[cc * 65 + tid] = 0.f;
            }
        }
        __syncthreads();

        if (tid < 64) {
            const int b_e = tid;
            float f0 = sig_ (pre[0 * 65 + b_e] + zf.x);
            float f1 = sig_ (pre[1 * 65 + b_e] + zf.y);
            float i0 = sig_ (pre[2 * 65 + b_e] + zi.x);
            float i1 = sig_ (pre[3 * 65 + b_e] + zi.y);
            float g0 = tanh_(pre[4 * 65 + b_e] + zg.x);
            float g1 = tanh_(pre[5 * 65 + b_e] + zg.y);
            float o0 = sig_ (pre[6 * 65 + b_e] + zo.x);
            float o1 = sig_ (pre[7 * 65 + b_e] + zo.y);
            cst.x = f0 * cst.x + i0 * g0;
            cst.y = f1 * cst.y + i1 * g1;
            float h0 = o0 * tanh_(cst.x);
            float h1 = o1 * tanh_(cst.y);
            float2 h2 = {h0, h1};
            *(float2*)&g_h[(t + 1) & 1][b_e * 256 + u0]       = h2;
            *(float2*)&out[((size_t)t * 64 + b_e) * 256 + u0] = h2;
            if (t == TT - 1) {
                *(float2*)&out[TBH + b_e * 256 + u0]      = h2;
                *(float2*)&out[TBH + BH + b_e * 256 + u0] = cst;
            }
        }

        __syncthreads();     // epilogue stores done before release
        if (tid == 0) {
            asm volatile("red.release.gpu.global.add.u32 [%0], %1;"
                         :: "l"(&g_cnt), "r"(1u) : "memory");
        }
    }
}

// ---------------------------------------------------------------------------
// Launch
// ---------------------------------------------------------------------------
extern "C" void kernel_launch(void* const* d_in, const int* in_sizes, int n_in,
                              void* d_out, int out_size)
{
    const float* x  = (const float*)d_in[0];
    const float* Wf = (const float*)d_in[1];
    const float* bf = (const float*)d_in[2];
    const float* Wi = (const float*)d_in[3];
    const float* bi = (const float*)d_in[4];
    const float* Wg = (const float*)d_in[5];
    const float* bg = (const float*)d_in[6];
    const float* Wo = (const float*)d_in[7];
    const float* bo = (const float*)d_in[8];
    float* out = (float*)d_out;

    static bool attr_set = false;
    if (!attr_set) {
        cudaFuncSetAttribute(lstm_kernel,
                             cudaFuncAttributeMaxDynamicSharedMemorySize,
                             SMEM_FLOATS * (int)sizeof(float));
        attr_set = true;
    }

    proj_kernel<<<dim3(8, 512), 256>>>(x, Wf, bf, Wi, bi, Wg, bg, Wo, bo);
    lstm_kernel<<<NBLK, 512, SMEM_FLOATS * sizeof(float)>>>(Wf, Wi, Wg, Wo, out);
}